// round 4
// baseline (speedup 1.0000x reference)
#include <cuda_runtime.h>

#define NN   8192
#define DD   128
#define TILE 128
#define NT   (NN / TILE)      // 64 row/col tiles
#define NTRI (NT * (NT + 1) / 2)  // 2080 triangular tiles
#define BK   16
#define LDS_STRIDE 132        // padded row stride (floats), keeps 16B alignment

// Scratch (device globals: no allocation allowed in kernel_launch)
__device__ unsigned g_maxpos[NN];  // running max of d^2 over positives (bits of fp32 >= 0)
__device__ unsigned g_minneg[NN];  // running min of d^2 over negatives
__device__ float    g_sq[NN];      // squared norms
__device__ int      g_lab[NN];     // labels as int32

// ---------------------------------------------------------------------------
// Kernel 1: squared norms, label copy, scratch init. One warp per row.
// NOTE: labels are int32 on device (JAX x64 disabled downgrades int64->int32).
// ---------------------------------------------------------------------------
__global__ void tl_init_kernel(const float* __restrict__ emb,
                               const int* __restrict__ lab) {
    int row  = (blockIdx.x * blockDim.x + threadIdx.x) >> 5;
    int lane = threadIdx.x & 31;
    if (row >= NN) return;
    float4 v = reinterpret_cast<const float4*>(emb + (size_t)row * DD)[lane];
    float s = v.x * v.x + v.y * v.y + v.z * v.z + v.w * v.w;
#pragma unroll
    for (int o = 16; o > 0; o >>= 1) s += __shfl_xor_sync(0xffffffffu, s, o);
    if (lane == 0) {
        g_sq[row]     = s;
        g_lab[row]    = lab[row];
        g_maxpos[row] = 0u;                       // bits of 0.0f
        g_minneg[row] = __float_as_uint(1e30f);   // "no negative seen"
    }
}

// ---------------------------------------------------------------------------
// Kernel 2: triangular 128x128 tiles of d^2 = sq_r + sq_c - 2*<x_r, x_c>,
// fused masked max/min reduction for BOTH the row range and the col range
// (symmetry), pushed to global via uint atomicMax/atomicMin.
// ---------------------------------------------------------------------------
__global__ void __launch_bounds__(256, 2)
tl_tile_kernel(const float* __restrict__ emb) {
    __shared__ float As[BK][LDS_STRIDE];
    __shared__ float Bs[BK][LDS_STRIDE];
    __shared__ unsigned sRowMax[TILE], sRowMin[TILE];
    __shared__ unsigned sColMax[TILE], sColMin[TILE];

    // ---- decode triangular block index -> (r, c) with c >= r ----
    int idx = blockIdx.x;
    float disc = (float)((2 * NT + 1) * (2 * NT + 1)) - 8.0f * (float)idx;
    int r = (int)(((float)(2 * NT + 1) - sqrtf(disc)) * 0.5f);
    if (r < 0) r = 0;
    if (r > NT - 1) r = NT - 1;
    while (r > 0 && r * NT - r * (r - 1) / 2 > idx) r--;
    while ((r + 1) * NT - (r + 1) * r / 2 <= idx) r++;
    int c = r + (idx - (r * NT - r * (r - 1) / 2));

    const int rowBase = r * TILE;
    const int colBase = c * TILE;

    const int tid = threadIdx.x;
    const int tx  = tid & 15;   // col group
    const int ty  = tid >> 4;   // row group

    if (tid < TILE) {
        sRowMax[tid] = 0u;
        sColMax[tid] = 0u;
        sRowMin[tid] = __float_as_uint(1e30f);
        sColMin[tid] = __float_as_uint(1e30f);
    }

    float acc[8][8];
#pragma unroll
    for (int i = 0; i < 8; i++)
#pragma unroll
        for (int j = 0; j < 8; j++) acc[i][j] = 0.0f;

    // ---- K loop: 8 chunks of BK=16 ----
    for (int kc = 0; kc < DD; kc += BK) {
        __syncthreads();
        // load 128 rows x 16 k, transposed into As[k][row]; same for Bs (cols)
#pragma unroll
        for (int it = 0; it < 2; it++) {
            int f  = tid + it * 256;       // 0..511 float4 slots
            int rr = f >> 2;               // 0..127
            int k4 = (f & 3) * 4;          // 0,4,8,12
            float4 va = *reinterpret_cast<const float4*>(
                emb + (size_t)(rowBase + rr) * DD + kc + k4);
            As[k4 + 0][rr] = va.x; As[k4 + 1][rr] = va.y;
            As[k4 + 2][rr] = va.z; As[k4 + 3][rr] = va.w;
            float4 vb = *reinterpret_cast<const float4*>(
                emb + (size_t)(colBase + rr) * DD + kc + k4);
            Bs[k4 + 0][rr] = vb.x; Bs[k4 + 1][rr] = vb.y;
            Bs[k4 + 2][rr] = vb.z; Bs[k4 + 3][rr] = vb.w;
        }
        __syncthreads();

#pragma unroll
        for (int k = 0; k < BK; k++) {
            float a[8], b[8];
            *reinterpret_cast<float4*>(&a[0]) =
                *reinterpret_cast<const float4*>(&As[k][ty * 4]);
            *reinterpret_cast<float4*>(&a[4]) =
                *reinterpret_cast<const float4*>(&As[k][64 + ty * 4]);
            *reinterpret_cast<float4*>(&b[0]) =
                *reinterpret_cast<const float4*>(&Bs[k][tx * 4]);
            *reinterpret_cast<float4*>(&b[4]) =
                *reinterpret_cast<const float4*>(&Bs[k][64 + tx * 4]);
#pragma unroll
            for (int i = 0; i < 8; i++)
#pragma unroll
                for (int j = 0; j < 8; j++) acc[i][j] += a[i] * b[j];
        }
    }

    // ---- epilogue: d^2, label masks, per-thread running max/min ----
    int lrow[8], lcol[8];
#pragma unroll
    for (int i = 0; i < 4; i++) {
        lrow[i]     = ty * 4 + i;
        lrow[i + 4] = 64 + ty * 4 + i;
        lcol[i]     = tx * 4 + i;
        lcol[i + 4] = 64 + tx * 4 + i;
    }
    float sqr[8], sqc[8];
    int   lr[8], lc[8];
#pragma unroll
    for (int i = 0; i < 8; i++) {
        sqr[i] = g_sq[rowBase + lrow[i]];
        lr[i]  = g_lab[rowBase + lrow[i]];
        sqc[i] = g_sq[colBase + lcol[i]];
        lc[i]  = g_lab[colBase + lcol[i]];
    }

    float rMaxPos[8], rMinNeg[8], cMaxPos[8], cMinNeg[8];
#pragma unroll
    for (int i = 0; i < 8; i++) {
        rMaxPos[i] = 0.0f;   rMinNeg[i] = 1e30f;
        cMaxPos[i] = 0.0f;   cMinNeg[i] = 1e30f;
    }

#pragma unroll
    for (int i = 0; i < 8; i++) {
        const int gr = rowBase + lrow[i];
#pragma unroll
        for (int j = 0; j < 8; j++) {
            const int gc = colBase + lcol[j];
            float d2 = fmaxf(sqr[i] + sqc[j] - 2.0f * acc[i][j], 0.0f);
            if (lr[i] == lc[j]) {
                if (gr != gc) {  // exclude self from positives
                    rMaxPos[i] = fmaxf(rMaxPos[i], d2);
                    cMaxPos[j] = fmaxf(cMaxPos[j], d2);
                }
            } else {
                rMinNeg[i] = fminf(rMinNeg[i], d2);
                cMinNeg[j] = fminf(cMinNeg[j], d2);
            }
        }
    }

    // shared reduction (uint-ordered: all values are non-negative floats)
#pragma unroll
    for (int i = 0; i < 8; i++) {
        atomicMax(&sRowMax[lrow[i]], __float_as_uint(rMaxPos[i]));
        atomicMin(&sRowMin[lrow[i]], __float_as_uint(rMinNeg[i]));
        atomicMax(&sColMax[lcol[i]], __float_as_uint(cMaxPos[i]));
        atomicMin(&sColMin[lcol[i]], __float_as_uint(cMinNeg[i]));
    }
    __syncthreads();

    if (tid < TILE) {
        atomicMax(&g_maxpos[rowBase + tid], sRowMax[tid]);
        atomicMin(&g_minneg[rowBase + tid], sRowMin[tid]);
    } else {
        int t = tid - TILE;
        atomicMax(&g_maxpos[colBase + t], sColMax[t]);
        atomicMin(&g_minneg[colBase + t], sColMin[t]);
    }
}

// ---------------------------------------------------------------------------
// Kernel 3: per-row sqrt + hinge, mean over N, single block.
// ---------------------------------------------------------------------------
__global__ void tl_final_kernel(const float* __restrict__ margin_ptr,
                                float* __restrict__ out) {
    const float m = *margin_ptr;
    float sum = 0.0f;
    for (int r = threadIdx.x; r < NN; r += 256) {
        float pos = sqrtf(__uint_as_float(g_maxpos[r]));
        float neg = sqrtf(__uint_as_float(g_minneg[r]));
        sum += fmaxf(pos - neg + m, 0.0f);
    }
    __shared__ float red[256];
    red[threadIdx.x] = sum;
    __syncthreads();
    for (int s = 128; s > 0; s >>= 1) {
        if (threadIdx.x < s) red[threadIdx.x] += red[threadIdx.x + s];
        __syncthreads();
    }
    if (threadIdx.x == 0) out[0] = red[0] / (float)NN;
}

// ---------------------------------------------------------------------------
extern "C" void kernel_launch(void* const* d_in, const int* in_sizes, int n_in,
                              void* d_out, int out_size) {
    const float* emb    = (const float*)d_in[0];
    const int*   labels = (const int*)d_in[1];     // int32 (JAX x64 off)
    const float* margin = (const float*)d_in[2];
    float*       out    = (float*)d_out;

    // 8 warps/block -> 8 rows/block -> NN/8 blocks
    tl_init_kernel<<<NN / 8, 256>>>(emb, labels);
    tl_tile_kernel<<<NTRI, 256>>>(emb);
    tl_final_kernel<<<1, 256>>>(margin, out);
}

// round 10
// speedup vs baseline: 1.4186x; 1.4186x over previous
#include <cuda_runtime.h>
#include <cuda_bf16.h>
#include <cstdint>

#define NN   8192
#define DD   128
#define TILE 128
#define NT   (NN / TILE)           // 64
#define NTRI (NT * (NT + 1) / 2)   // 2080

// ---------------- smem layout ----------------
// bf16 tiles [128 rows][136 elems] (272B row stride: 16B aligned, and 272%128=16
// so 8 consecutive rows hit distinct 16B segments -> conflict-free ldmatrix)
#define T_STRIDE   136
#define T_ROWBYTES (T_STRIDE * 2)              // 272
#define T_BYTES    (TILE * T_ROWBYTES)         // 34816
#define SM_A_HI    0
#define SM_A_LO    (1 * T_BYTES)
#define SM_B_HI    (2 * T_BYTES)
#define SM_B_LO    (3 * T_BYTES)
#define AUX        (4 * T_BYTES)               // 139264
#define AUX_SQR    (AUX + 0)
#define AUX_SQC    (AUX + 512)
#define AUX_LR     (AUX + 1024)
#define AUX_LC     (AUX + 1536)
#define SMEM_BYTES (AUX + 2048)
// staged dot matrix (fp32, stride 130) overlaps the A tiles after MMA is done
#define D_STRIDE   130

// ---------------- device scratch ----------------
__device__ unsigned      g_maxpos[NN];
__device__ unsigned      g_minneg[NN];
__device__ float         g_sq[NN];
__device__ int           g_lab[NN];
__device__ __nv_bfloat16 g_hi[NN * DD];
__device__ __nv_bfloat16 g_lo[NN * DD];

__device__ __forceinline__ uint32_t smem_u32(const void* p) {
    uint32_t a;
    asm("{ .reg .u64 t; cvta.to.shared.u64 t, %1; cvt.u32.u64 %0, t; }" : "=r"(a) : "l"(p));
    return a;
}
__device__ __forceinline__ void ldmx4(uint32_t* r, uint32_t addr) {
    asm volatile("ldmatrix.sync.aligned.m8n8.x4.shared.b16 {%0,%1,%2,%3}, [%4];"
                 : "=r"(r[0]), "=r"(r[1]), "=r"(r[2]), "=r"(r[3]) : "r"(addr));
}
__device__ __forceinline__ void mma16816(float* c, const uint32_t* a,
                                         uint32_t b0, uint32_t b1) {
    asm volatile(
        "mma.sync.aligned.m16n8k16.row.col.f32.bf16.bf16.f32 "
        "{%0,%1,%2,%3}, {%4,%5,%6,%7}, {%8,%9}, {%0,%1,%2,%3};"
        : "+f"(c[0]), "+f"(c[1]), "+f"(c[2]), "+f"(c[3])
        : "r"(a[0]), "r"(a[1]), "r"(a[2]), "r"(a[3]), "r"(b0), "r"(b1));
}

// ---------------------------------------------------------------------------
// Kernel 1: squared norms, labels, bf16 hi/lo split, scratch init. Warp/row.
// ---------------------------------------------------------------------------
__global__ void tl_init_kernel(const float* __restrict__ emb,
                               const int* __restrict__ lab) {
    int row  = (blockIdx.x * blockDim.x + threadIdx.x) >> 5;
    int lane = threadIdx.x & 31;
    if (row >= NN) return;
    float4 v = reinterpret_cast<const float4*>(emb + (size_t)row * DD)[lane];
    float s = v.x * v.x + v.y * v.y + v.z * v.z + v.w * v.w;

    float xs[4] = {v.x, v.y, v.z, v.w};
    __nv_bfloat16 hi[4], lo[4];
#pragma unroll
    for (int i = 0; i < 4; i++) {
        hi[i] = __float2bfloat16(xs[i]);
        lo[i] = __float2bfloat16(xs[i] - __bfloat162float(hi[i]));
    }
    size_t o = (size_t)row * DD + lane * 4;
    *reinterpret_cast<uint2*>(&g_hi[o]) = *reinterpret_cast<uint2*>(hi);
    *reinterpret_cast<uint2*>(&g_lo[o]) = *reinterpret_cast<uint2*>(lo);

#pragma unroll
    for (int off = 16; off > 0; off >>= 1) s += __shfl_xor_sync(0xffffffffu, s, off);
    if (lane == 0) {
        g_sq[row]     = s;
        g_lab[row]    = lab[row];
        g_maxpos[row] = 0u;
        g_minneg[row] = __float_as_uint(1e30f);
    }
}

// ---------------------------------------------------------------------------
// Kernel 2: one 128x128 triangular tile per CTA. 3-pass bf16 split GEMM on
// mma.sync.m16n8k16 (tensor pipe, valid on compute_103). 8 warps in a 2x4
// grid, 64x32 output per warp, fp32 accumulators in registers. Epilogue
// stages dots to smem, then 128 row-threads + 128 col-threads do the masked
// max/min reductions (symmetric tile serves both ranges) -> global atomics.
// ---------------------------------------------------------------------------
__global__ void __launch_bounds__(256, 1)
tl_tile_mma() {
    extern __shared__ char smem[];
    const uint32_t sb = smem_u32(smem);
    const int tid = threadIdx.x, wid = tid >> 5, lane = tid & 31;

    // ---- triangular decode ----
    int idx = blockIdx.x;
    float disc = (float)((2 * NT + 1) * (2 * NT + 1)) - 8.0f * (float)idx;
    int r = (int)(((float)(2 * NT + 1) - sqrtf(disc)) * 0.5f);
    if (r < 0) r = 0;
    if (r > NT - 1) r = NT - 1;
    while (r > 0 && r * NT - r * (r - 1) / 2 > idx) r--;
    while ((r + 1) * NT - (r + 1) * r / 2 <= idx) r++;
    const int c = r + (idx - (r * NT - r * (r - 1) / 2));
    const int rowBase = r * TILE;
    const int colBase = c * TILE;

    // ---- fill 4 bf16 tiles: A_hi, A_lo, B_hi, B_lo ([row][k], stride 136) ----
    // i -> (buf, row, 16B chunk). Coalesced gmem reads, conflict-free STS.128.
    for (int i = tid; i < 4 * 2048; i += 256) {
        int buf = i >> 11, idx2 = i & 2047, row = idx2 >> 4, ch = idx2 & 15;
        int base = (buf < 2) ? rowBase : colBase;
        const __nv_bfloat16* src = (buf & 1) ? g_lo : g_hi;
        uint4 v = *reinterpret_cast<const uint4*>(src + (size_t)(base + row) * DD + ch * 8);
        *reinterpret_cast<uint4*>(smem + buf * T_BYTES + row * T_ROWBYTES + ch * 16) = v;
    }
    if (tid < 128) {
        ((float*)(smem + AUX_SQR))[tid] = g_sq[rowBase + tid];
        ((float*)(smem + AUX_SQC))[tid] = g_sq[colBase + tid];
        ((int*)(smem + AUX_LR))[tid]    = g_lab[rowBase + tid];
        ((int*)(smem + AUX_LC))[tid]    = g_lab[colBase + tid];
    }
    __syncthreads();

    // ---- MMA: warp (wm, wn) owns a 64x32 block; 4 m-blocks x 4 n-blocks ----
    const int wm = wid >> 2, wn = wid & 3;
    float acc[4][4][4];
#pragma unroll
    for (int mb = 0; mb < 4; mb++)
#pragma unroll
        for (int nb = 0; nb < 4; nb++)
#pragma unroll
            for (int q = 0; q < 4; q++) acc[mb][nb][q] = 0.0f;

    // ldmatrix lane addressing (bytes within a tile buffer):
    // A x4 (m16k16): lanes 0-15 -> rows m+0..15 @k0, lanes 16-31 -> same rows @k0+8
    const uint32_t a_off = (uint32_t)(wm * 64 + (lane & 15)) * T_ROWBYTES
                         + ((lane >> 4) << 4);
    // B x4 (two n8k16 blocks): row n + (lane&7) + 8*(lane>=16), k half = (lane>>3)&1
    const uint32_t b_off = (uint32_t)(wn * 32 + (lane & 7) + ((lane >> 4) << 3)) * T_ROWBYTES
                         + (((lane >> 3) & 1) << 4);

    const uint32_t aoffs[3] = {SM_A_HI, SM_A_HI, SM_A_LO};
    const uint32_t boffs[3] = {SM_B_HI, SM_B_LO, SM_B_HI};

#pragma unroll
    for (int p = 0; p < 3; p++) {
        const uint32_t abase = sb + aoffs[p] + a_off;
        const uint32_t bbase = sb + boffs[p] + b_off;
#pragma unroll
        for (int ks = 0; ks < 8; ks++) {
            uint32_t a[4][4], b[2][4];
#pragma unroll
            for (int mb = 0; mb < 4; mb++)
                ldmx4(a[mb], abase + mb * (16 * T_ROWBYTES) + ks * 32);
#pragma unroll
            for (int n2 = 0; n2 < 2; n2++)
                ldmx4(b[n2], bbase + n2 * (16 * T_ROWBYTES) + ks * 32);
#pragma unroll
            for (int mb = 0; mb < 4; mb++)
#pragma unroll
                for (int nb = 0; nb < 4; nb++)
                    mma16816(acc[mb][nb], a[mb], b[nb >> 1][(nb & 1) * 2],
                             b[nb >> 1][(nb & 1) * 2 + 1]);
        }
    }
    __syncthreads();   // all warps done reading tiles before dots overwrite them

    // ---- stage dots to smem (fp32 [128][130], overlaps dead A tiles) ----
    {
        float* dots = reinterpret_cast<float*>(smem);
        const int r0 = wm * 64 + (lane >> 2);
        const int c0 = wn * 32 + 2 * (lane & 3);
#pragma unroll
        for (int mb = 0; mb < 4; mb++)
#pragma unroll
            for (int nb = 0; nb < 4; nb++) {
                int rr = r0 + mb * 16, cc = c0 + nb * 8;
                *reinterpret_cast<float2*>(&dots[rr * D_STRIDE + cc]) =
                    make_float2(acc[mb][nb][0], acc[mb][nb][1]);
                *reinterpret_cast<float2*>(&dots[(rr + 8) * D_STRIDE + cc]) =
                    make_float2(acc[mb][nb][2], acc[mb][nb][3]);
            }
    }
    __syncthreads();

    // ---- masked row/col reductions over staged dots ----
    const float* dots = reinterpret_cast<const float*>(smem);
    const float* sqr  = (const float*)(smem + AUX_SQR);
    const float* sqc  = (const float*)(smem + AUX_SQC);
    const int*   lr   = (const int*)(smem + AUX_LR);
    const int*   lc   = (const int*)(smem + AUX_LC);

    if (tid < 128) {                       // row side
        const int rr = tid, gr = rowBase + rr;
        const int   myl  = lr[rr];
        const float mysq = sqr[rr];
        float pmax = 0.0f, nmin = 1e30f;
        const float* row_p = dots + rr * D_STRIDE;
#pragma unroll 4
        for (int n = 0; n < 128; n++) {
            float d2 = fmaxf(mysq + sqc[n] - 2.0f * row_p[n], 0.0f);
            if (myl == lc[n]) {
                if (gr != colBase + n) pmax = fmaxf(pmax, d2);
            } else {
                nmin = fminf(nmin, d2);
            }
        }
        atomicMax(&g_maxpos[gr], __float_as_uint(pmax));
        atomicMin(&g_minneg[gr], __float_as_uint(nmin));
    } else {                               // col side (symmetry)
        const int j = tid - 128, gc = colBase + j;
        const int   myl  = lc[j];
        const float mysq = sqc[j];
        float pmax = 0.0f, nmin = 1e30f;
#pragma unroll 4
        for (int m2 = 0; m2 < 128; m2++) {
            float d2 = fmaxf(mysq + sqr[m2] - 2.0f * dots[m2 * D_STRIDE + j], 0.0f);
            if (myl == lr[m2]) {
                if (rowBase + m2 != gc) pmax = fmaxf(pmax, d2);
            } else {
                nmin = fminf(nmin, d2);
            }
        }
        atomicMax(&g_maxpos[gc], __float_as_uint(pmax));
        atomicMin(&g_minneg[gc], __float_as_uint(nmin));
    }
}

// ---------------------------------------------------------------------------
// Kernel 3: per-row sqrt + hinge, mean over N.
// ---------------------------------------------------------------------------
__global__ void tl_final_kernel(const float* __restrict__ margin_ptr,
                                float* __restrict__ out) {
    const float m = *margin_ptr;
    float sum = 0.0f;
    for (int r = threadIdx.x; r < NN; r += 256) {
        float pos = sqrtf(__uint_as_float(g_maxpos[r]));
        float neg = sqrtf(__uint_as_float(g_minneg[r]));
        sum += fmaxf(pos - neg + m, 0.0f);
    }
    __shared__ float red[256];
    red[threadIdx.x] = sum;
    __syncthreads();
    for (int s = 128; s > 0; s >>= 1) {
        if (threadIdx.x < s) red[threadIdx.x] += red[threadIdx.x + s];
        __syncthreads();
    }
    if (threadIdx.x == 0) out[0] = red[0] / (float)NN;
}

// ---------------------------------------------------------------------------
extern "C" void kernel_launch(void* const* d_in, const int* in_sizes, int n_in,
                              void* d_out, int out_size) {
    const float* emb    = (const float*)d_in[0];
    const int*   labels = (const int*)d_in[1];
    const float* margin = (const float*)d_in[2];
    float*       out    = (float*)d_out;

    cudaFuncSetAttribute(tl_tile_mma, cudaFuncAttributeMaxDynamicSharedMemorySize,
                         SMEM_BYTES);

    tl_init_kernel<<<NN / 8, 256>>>(emb, labels);
    tl_tile_mma<<<NTRI, 256, SMEM_BYTES>>>();
    tl_final_kernel<<<1, 256>>>(margin, out);
}

// round 11
// speedup vs baseline: 1.5381x; 1.0842x over previous
#include <cuda_runtime.h>
#include <cuda_bf16.h>
#include <cstdint>

#define NN   8192
#define DD   128
#define TILE 128
#define NT   (NN / TILE)           // 64
#define NTRI (NT * (NT + 1) / 2)   // 2080

// ---------------- smem layout (per CTA, K processed in 2 chunks of 64) ------
// bf16 K-chunk tiles [128 rows][72 elems] (144B stride: 16B aligned, 144%128=16
// so 8 consecutive rows hit distinct 16B segments -> conflict-free ldmatrix)
#define T2_ROWBYTES 144
#define T2_BYTES    (TILE * T2_ROWBYTES)       // 18432
#define SM_A_HI     0
#define SM_A_LO     (1 * T2_BYTES)
#define SM_B_HI     (2 * T2_BYTES)
#define SM_B_LO     (3 * T2_BYTES)
#define AUX         (4 * T2_BYTES)             // 73728
#define AUX_SQR     (AUX + 0)
#define AUX_SQC     (AUX + 512)
#define AUX_LR      (AUX + 1024)
#define AUX_LC      (AUX + 1536)
#define SMEM_BYTES  (AUX + 2048)               // 75776 -> 2 CTAs/SM
// staged fp32 dot matrix (stride 130 -> 66560 B) overlaps dead tiles
#define D_STRIDE    130

// ---------------- device scratch ----------------
__device__ unsigned      g_maxpos[NN];
__device__ unsigned      g_minneg[NN];
__device__ float         g_sq[NN];
__device__ int           g_lab[NN];
__device__ __nv_bfloat16 g_hi[NN * DD];
__device__ __nv_bfloat16 g_lo[NN * DD];

__device__ __forceinline__ uint32_t smem_u32(const void* p) {
    uint32_t a;
    asm("{ .reg .u64 t; cvta.to.shared.u64 t, %1; cvt.u32.u64 %0, t; }" : "=r"(a) : "l"(p));
    return a;
}
__device__ __forceinline__ void ldmx4(uint32_t* r, uint32_t addr) {
    asm volatile("ldmatrix.sync.aligned.m8n8.x4.shared.b16 {%0,%1,%2,%3}, [%4];"
                 : "=r"(r[0]), "=r"(r[1]), "=r"(r[2]), "=r"(r[3]) : "r"(addr));
}
__device__ __forceinline__ void mma16816(float* c, const uint32_t* a,
                                         uint32_t b0, uint32_t b1) {
    asm volatile(
        "mma.sync.aligned.m16n8k16.row.col.f32.bf16.bf16.f32 "
        "{%0,%1,%2,%3}, {%4,%5,%6,%7}, {%8,%9}, {%0,%1,%2,%3};"
        : "+f"(c[0]), "+f"(c[1]), "+f"(c[2]), "+f"(c[3])
        : "r"(a[0]), "r"(a[1]), "r"(a[2]), "r"(a[3]), "r"(b0), "r"(b1));
}
#define CP_ASYNC16(dst, src) \
    asm volatile("cp.async.cg.shared.global [%0], [%1], 16;" :: "r"(dst), "l"(src))
#define CP_COMMIT_WAIT() do {                                   \
    asm volatile("cp.async.commit_group;" ::: "memory");        \
    asm volatile("cp.async.wait_group 0;" ::: "memory");        \
} while (0)

// ---------------------------------------------------------------------------
// Kernel 1: squared norms, labels, bf16 hi/lo split, scratch init. Warp/row.
// ---------------------------------------------------------------------------
__global__ void tl_init_kernel(const float* __restrict__ emb,
                               const int* __restrict__ lab) {
    int row  = (blockIdx.x * blockDim.x + threadIdx.x) >> 5;
    int lane = threadIdx.x & 31;
    if (row >= NN) return;
    float4 v = reinterpret_cast<const float4*>(emb + (size_t)row * DD)[lane];
    float s = v.x * v.x + v.y * v.y + v.z * v.z + v.w * v.w;

    float xs[4] = {v.x, v.y, v.z, v.w};
    __nv_bfloat16 hi[4], lo[4];
#pragma unroll
    for (int i = 0; i < 4; i++) {
        hi[i] = __float2bfloat16(xs[i]);
        lo[i] = __float2bfloat16(xs[i] - __bfloat162float(hi[i]));
    }
    size_t o = (size_t)row * DD + lane * 4;
    *reinterpret_cast<uint2*>(&g_hi[o]) = *reinterpret_cast<uint2*>(hi);
    *reinterpret_cast<uint2*>(&g_lo[o]) = *reinterpret_cast<uint2*>(lo);

#pragma unroll
    for (int off = 16; off > 0; off >>= 1) s += __shfl_xor_sync(0xffffffffu, s, off);
    if (lane == 0) {
        g_sq[row]     = s;
        g_lab[row]    = lab[row];
        g_maxpos[row] = 0u;
        g_minneg[row] = __float_as_uint(1e30f);
    }
}

// ---------------------------------------------------------------------------
// Kernel 2: one 128x128 triangular tile per CTA. 3-pass bf16 split GEMM on
// mma.sync.m16n8k16, K processed as 2 chunks of 64 so smem fits 2 CTAs/SM
// (cross-CTA overlap of fill / MMA / epilogue phases). cp.async tile fill.
// Epilogue: stage dots to smem, 128 row-threads + 128 col-threads do masked
// max/min reductions (symmetric tile serves both ranges) -> global atomics.
// ---------------------------------------------------------------------------
__global__ void __launch_bounds__(256, 2)
tl_tile_mma() {
    extern __shared__ char smem[];
    const uint32_t sb = smem_u32(smem);
    const int tid = threadIdx.x, wid = tid >> 5, lane = tid & 31;

    // ---- triangular decode ----
    int idx = blockIdx.x;
    float disc = (float)((2 * NT + 1) * (2 * NT + 1)) - 8.0f * (float)idx;
    int r = (int)(((float)(2 * NT + 1) - sqrtf(disc)) * 0.5f);
    if (r < 0) r = 0;
    if (r > NT - 1) r = NT - 1;
    while (r > 0 && r * NT - r * (r - 1) / 2 > idx) r--;
    while ((r + 1) * NT - (r + 1) * r / 2 <= idx) r++;
    const int c = r + (idx - (r * NT - r * (r - 1) / 2));
    const int rowBase = r * TILE;
    const int colBase = c * TILE;

    if (tid < 128) {
        ((float*)(smem + AUX_SQR))[tid] = g_sq[rowBase + tid];
        ((float*)(smem + AUX_SQC))[tid] = g_sq[colBase + tid];
        ((int*)(smem + AUX_LR))[tid]    = g_lab[rowBase + tid];
        ((int*)(smem + AUX_LC))[tid]    = g_lab[colBase + tid];
    }

    // ---- warp tiling: warp (wm, wn) owns a 64x32 output block ----
    const int wm = wid >> 2, wn = wid & 3;
    float acc[4][4][4];
#pragma unroll
    for (int mb = 0; mb < 4; mb++)
#pragma unroll
        for (int nb = 0; nb < 4; nb++)
#pragma unroll
            for (int q = 0; q < 4; q++) acc[mb][nb][q] = 0.0f;

    // ldmatrix lane addressing (bytes within a tile buffer)
    const uint32_t a_off = (uint32_t)(wm * 64 + (lane & 15)) * T2_ROWBYTES
                         + ((lane >> 4) << 4);
    const uint32_t b_off = (uint32_t)(wn * 32 + (lane & 7) + ((lane >> 4) << 3)) * T2_ROWBYTES
                         + (((lane >> 3) & 1) << 4);

    const uint32_t aoffs[3] = {SM_A_HI, SM_A_HI, SM_A_LO};
    const uint32_t boffs[3] = {SM_B_HI, SM_B_LO, SM_B_HI};

    // ---- 2 K-chunks of 64: fill 4 bufs (cp.async), then 3x4 MMA ksteps ----
    for (int kc = 0; kc < 2; kc++) {
        if (kc) __syncthreads();   // previous chunk's reads done before refill
        // fill: 4 bufs x 128 rows x 8 chunks of 16B = 4096 cp.async
        for (int i = tid; i < 4096; i += 256) {
            int buf = i >> 10, rc2 = i & 1023, row = rc2 >> 3, ch = rc2 & 7;
            int base = (buf < 2) ? rowBase : colBase;
            const __nv_bfloat16* src = (buf & 1) ? g_lo : g_hi;
            const void* g = src + (size_t)(base + row) * DD + kc * 64 + ch * 8;
            uint32_t d = sb + buf * T2_BYTES + row * T2_ROWBYTES + ch * 16;
            CP_ASYNC16(d, g);
        }
        CP_COMMIT_WAIT();
        __syncthreads();

#pragma unroll
        for (int p = 0; p < 3; p++) {
            const uint32_t abase = sb + aoffs[p] + a_off;
            const uint32_t bbase = sb + boffs[p] + b_off;
#pragma unroll
            for (int ks = 0; ks < 4; ks++) {
                uint32_t a[4][4], b[2][4];
#pragma unroll
                for (int mb = 0; mb < 4; mb++)
                    ldmx4(a[mb], abase + mb * (16 * T2_ROWBYTES) + ks * 32);
#pragma unroll
                for (int n2 = 0; n2 < 2; n2++)
                    ldmx4(b[n2], bbase + n2 * (16 * T2_ROWBYTES) + ks * 32);
#pragma unroll
                for (int mb = 0; mb < 4; mb++)
#pragma unroll
                    for (int nb = 0; nb < 4; nb++)
                        mma16816(acc[mb][nb], a[mb], b[nb >> 1][(nb & 1) * 2],
                                 b[nb >> 1][(nb & 1) * 2 + 1]);
            }
        }
    }
    __syncthreads();   // all warps done reading tiles before dots overwrite

    // ---- stage dots to smem (fp32 [128][130], overlaps dead tiles) ----
    {
        float* dots = reinterpret_cast<float*>(smem);
        const int r0 = wm * 64 + (lane >> 2);
        const int c0 = wn * 32 + 2 * (lane & 3);
#pragma unroll
        for (int mb = 0; mb < 4; mb++)
#pragma unroll
            for (int nb = 0; nb < 4; nb++) {
                int rr = r0 + mb * 16, cc = c0 + nb * 8;
                *reinterpret_cast<float2*>(&dots[rr * D_STRIDE + cc]) =
                    make_float2(acc[mb][nb][0], acc[mb][nb][1]);
                *reinterpret_cast<float2*>(&dots[(rr + 8) * D_STRIDE + cc]) =
                    make_float2(acc[mb][nb][2], acc[mb][nb][3]);
            }
    }
    __syncthreads();

    // ---- masked row/col reductions over staged dots ----
    const float* dots = reinterpret_cast<const float*>(smem);
    const float* sqr  = (const float*)(smem + AUX_SQR);
    const float* sqc  = (const float*)(smem + AUX_SQC);
    const int*   lr   = (const int*)(smem + AUX_LR);
    const int*   lc   = (const int*)(smem + AUX_LC);

    if (tid < 128) {                       // row side
        const int rr = tid, gr = rowBase + rr;
        const int   myl  = lr[rr];
        const float mysq = sqr[rr];
        float pmax = 0.0f, nmin = 1e30f;
        const float* row_p = dots + rr * D_STRIDE;
#pragma unroll 4
        for (int n = 0; n < 128; n++) {
            float d2 = fmaxf(mysq + sqc[n] - 2.0f * row_p[n], 0.0f);
            if (myl == lc[n]) {
                if (gr != colBase + n) pmax = fmaxf(pmax, d2);
            } else {
                nmin = fminf(nmin, d2);
            }
        }
        atomicMax(&g_maxpos[gr], __float_as_uint(pmax));
        atomicMin(&g_minneg[gr], __float_as_uint(nmin));
    } else {                               // col side (symmetry)
        const int j = tid - 128, gc = colBase + j;
        const int   myl  = lc[j];
        const float mysq = sqc[j];
        float pmax = 0.0f, nmin = 1e30f;
#pragma unroll 4
        for (int m2 = 0; m2 < 128; m2++) {
            float d2 = fmaxf(mysq + sqr[m2] - 2.0f * dots[m2 * D_STRIDE + j], 0.0f);
            if (myl == lr[m2]) {
                if (rowBase + m2 != gc) pmax = fmaxf(pmax, d2);
            } else {
                nmin = fminf(nmin, d2);
            }
        }
        atomicMax(&g_maxpos[gc], __float_as_uint(pmax));
        atomicMin(&g_minneg[gc], __float_as_uint(nmin));
    }
}

// ---------------------------------------------------------------------------
// Kernel 3: per-row sqrt + hinge, mean over N.
// ---------------------------------------------------------------------------
__global__ void tl_final_kernel(const float* __restrict__ margin_ptr,
                                float* __restrict__ out) {
    const float m = *margin_ptr;
    float sum = 0.0f;
    for (int r = threadIdx.x; r < NN; r += 256) {
        float pos = sqrtf(__uint_as_float(g_maxpos[r]));
        float neg = sqrtf(__uint_as_float(g_minneg[r]));
        sum += fmaxf(pos - neg + m, 0.0f);
    }
    __shared__ float red[256];
    red[threadIdx.x] = sum;
    __syncthreads();
    for (int s = 128; s > 0; s >>= 1) {
        if (threadIdx.x < s) red[threadIdx.x] += red[threadIdx.x + s];
        __syncthreads();
    }
    if (threadIdx.x == 0) out[0] = red[0] / (float)NN;
}

// ---------------------------------------------------------------------------
extern "C" void kernel_launch(void* const* d_in, const int* in_sizes, int n_in,
                              void* d_out, int out_size) {
    const float* emb    = (const float*)d_in[0];
    const int*   labels = (const int*)d_in[1];
    const float* margin = (const float*)d_in[2];
    float*       out    = (float*)d_out;

    cudaFuncSetAttribute(tl_tile_mma, cudaFuncAttributeMaxDynamicSharedMemorySize,
                         SMEM_BYTES);

    tl_init_kernel<<<NN / 8, 256>>>(emb, labels);
    tl_tile_mma<<<NTRI, 256, SMEM_BYTES>>>();
    tl_final_kernel<<<1, 256>>>(margin, out);
}

// round 12
// speedup vs baseline: 2.2197x; 1.4432x over previous
#include <cuda_runtime.h>
#include <cuda_bf16.h>
#include <cstdint>

#define NN   8192
#define DD   128
#define TILE 128
#define NT   (NN / TILE)           // 64
#define NTRI (NT * (NT + 1) / 2)   // 2080

// ---------------- smem layout (per CTA, K processed in 2 chunks of 64) ------
// bf16 K-chunk tiles [128 rows][72 elems] (144B stride: 16B aligned, 144%128=16
// so 8 consecutive rows hit distinct 16B segments -> conflict-free ldmatrix)
#define T2_ROWBYTES 144
#define T2_BYTES    (TILE * T2_ROWBYTES)       // 18432
#define SM_A_HI     0
#define SM_A_LO     (1 * T2_BYTES)
#define SM_B_HI     (2 * T2_BYTES)
#define SM_B_LO     (3 * T2_BYTES)
#define AUX         (4 * T2_BYTES)             // 73728
#define AUX_SQR     (AUX + 0)
#define AUX_SQC     (AUX + 512)
#define AUX_LR      (AUX + 1024)
#define AUX_LC      (AUX + 1536)
#define AUX_RMAX    (AUX + 2048)
#define AUX_RMIN    (AUX + 2560)
#define AUX_CMAX    (AUX + 3072)
#define AUX_CMIN    (AUX + 3584)
#define SMEM_BYTES  (AUX + 4096)               // 77824 -> 2 CTAs/SM

// ---------------- device scratch ----------------
__device__ unsigned      g_maxpos[NN];
__device__ unsigned      g_minneg[NN];
__device__ float         g_sq[NN];
__device__ int           g_lab[NN];
__device__ __nv_bfloat16 g_hi[NN * DD];
__device__ __nv_bfloat16 g_lo[NN * DD];

__device__ __forceinline__ uint32_t smem_u32(const void* p) {
    uint32_t a;
    asm("{ .reg .u64 t; cvta.to.shared.u64 t, %1; cvt.u32.u64 %0, t; }" : "=r"(a) : "l"(p));
    return a;
}
__device__ __forceinline__ void ldmx4(uint32_t* r, uint32_t addr) {
    asm volatile("ldmatrix.sync.aligned.m8n8.x4.shared.b16 {%0,%1,%2,%3}, [%4];"
                 : "=r"(r[0]), "=r"(r[1]), "=r"(r[2]), "=r"(r[3]) : "r"(addr));
}
__device__ __forceinline__ void mma16816(float* c, const uint32_t* a,
                                         uint32_t b0, uint32_t b1) {
    asm volatile(
        "mma.sync.aligned.m16n8k16.row.col.f32.bf16.bf16.f32 "
        "{%0,%1,%2,%3}, {%4,%5,%6,%7}, {%8,%9}, {%0,%1,%2,%3};"
        : "+f"(c[0]), "+f"(c[1]), "+f"(c[2]), "+f"(c[3])
        : "r"(a[0]), "r"(a[1]), "r"(a[2]), "r"(a[3]), "r"(b0), "r"(b1));
}
#define CP_ASYNC16(dst, src) \
    asm volatile("cp.async.cg.shared.global [%0], [%1], 16;" :: "r"(dst), "l"(src))
#define CP_COMMIT_WAIT() do {                                   \
    asm volatile("cp.async.commit_group;" ::: "memory");        \
    asm volatile("cp.async.wait_group 0;" ::: "memory");        \
} while (0)

// ---------------------------------------------------------------------------
// Kernel 1: squared norms, labels, bf16 hi/lo split, scratch init. Warp/row.
// ---------------------------------------------------------------------------
__global__ void tl_init_kernel(const float* __restrict__ emb,
                               const int* __restrict__ lab) {
    int row  = (blockIdx.x * blockDim.x + threadIdx.x) >> 5;
    int lane = threadIdx.x & 31;
    if (row >= NN) return;
    float4 v = reinterpret_cast<const float4*>(emb + (size_t)row * DD)[lane];
    float s = v.x * v.x + v.y * v.y + v.z * v.z + v.w * v.w;

    float xs[4] = {v.x, v.y, v.z, v.w};
    __nv_bfloat16 hi[4], lo[4];
#pragma unroll
    for (int i = 0; i < 4; i++) {
        hi[i] = __float2bfloat16(xs[i]);
        lo[i] = __float2bfloat16(xs[i] - __bfloat162float(hi[i]));
    }
    size_t o = (size_t)row * DD + lane * 4;
    *reinterpret_cast<uint2*>(&g_hi[o]) = *reinterpret_cast<uint2*>(hi);
    *reinterpret_cast<uint2*>(&g_lo[o]) = *reinterpret_cast<uint2*>(lo);

#pragma unroll
    for (int off = 16; off > 0; off >>= 1) s += __shfl_xor_sync(0xffffffffu, s, off);
    if (lane == 0) {
        g_sq[row]     = s;
        g_lab[row]    = lab[row];
        g_maxpos[row] = 0u;
        g_minneg[row] = __float_as_uint(1e30f);
    }
}

// ---------------------------------------------------------------------------
// Kernel 2: one 128x128 triangular tile per CTA. 3-pass bf16 split GEMM on
// mma.sync.m16n8k16 (K in 2 chunks of 64, 2 CTAs/SM). Fragment reuse:
// a_hi and b_hi loaded once per kstep, used by 2 passes each.
// Epilogue is register-resident: d^2 + label masks computed on the mma C
// fragments in place, reduced by warp shuffles, then smem max/min arrays,
// then global uint atomics (symmetric tile serves row AND col ranges).
// ---------------------------------------------------------------------------
__global__ void __launch_bounds__(256, 2)
tl_tile_mma() {
    extern __shared__ char smem[];
    const uint32_t sb = smem_u32(smem);
    const int tid = threadIdx.x, wid = tid >> 5, lane = tid & 31;

    // ---- triangular decode ----
    int idx = blockIdx.x;
    float disc = (float)((2 * NT + 1) * (2 * NT + 1)) - 8.0f * (float)idx;
    int r = (int)(((float)(2 * NT + 1) - sqrtf(disc)) * 0.5f);
    if (r < 0) r = 0;
    if (r > NT - 1) r = NT - 1;
    while (r > 0 && r * NT - r * (r - 1) / 2 > idx) r--;
    while ((r + 1) * NT - (r + 1) * r / 2 <= idx) r++;
    const int c = r + (idx - (r * NT - r * (r - 1) / 2));
    const int rowBase = r * TILE;
    const int colBase = c * TILE;

    if (tid < 128) {
        ((float*)(smem + AUX_SQR))[tid]      = g_sq[rowBase + tid];
        ((float*)(smem + AUX_SQC))[tid]      = g_sq[colBase + tid];
        ((int*)(smem + AUX_LR))[tid]         = g_lab[rowBase + tid];
        ((int*)(smem + AUX_LC))[tid]         = g_lab[colBase + tid];
        ((unsigned*)(smem + AUX_RMAX))[tid]  = 0u;
        ((unsigned*)(smem + AUX_RMIN))[tid]  = __float_as_uint(1e30f);
        ((unsigned*)(smem + AUX_CMAX))[tid]  = 0u;
        ((unsigned*)(smem + AUX_CMIN))[tid]  = __float_as_uint(1e30f);
    }

    // ---- warp tiling: warp (wm, wn) owns a 64x32 output block ----
    const int wm = wid >> 2, wn = wid & 3;
    float acc[4][4][4];
#pragma unroll
    for (int mb = 0; mb < 4; mb++)
#pragma unroll
        for (int nb = 0; nb < 4; nb++)
#pragma unroll
            for (int q = 0; q < 4; q++) acc[mb][nb][q] = 0.0f;

    // ldmatrix lane addressing (bytes within a tile buffer)
    const uint32_t a_off = (uint32_t)(wm * 64 + (lane & 15)) * T2_ROWBYTES
                         + ((lane >> 4) << 4);
    const uint32_t b_off = (uint32_t)(wn * 32 + (lane & 7) + ((lane >> 4) << 3)) * T2_ROWBYTES
                         + (((lane >> 3) & 1) << 4);

    // ---- 2 K-chunks of 64: fill 4 bufs (cp.async), then MMA ksteps ----
    for (int kc = 0; kc < 2; kc++) {
        if (kc) __syncthreads();   // previous chunk's reads done before refill
        for (int i = tid; i < 4096; i += 256) {
            int buf = i >> 10, rc2 = i & 1023, row = rc2 >> 3, ch = rc2 & 7;
            int base = (buf < 2) ? rowBase : colBase;
            const __nv_bfloat16* src = (buf & 1) ? g_lo : g_hi;
            const void* g = src + (size_t)(base + row) * DD + kc * 64 + ch * 8;
            uint32_t d = sb + buf * T2_BYTES + row * T2_ROWBYTES + ch * 16;
            CP_ASYNC16(d, g);
        }
        CP_COMMIT_WAIT();
        __syncthreads();

        const uint32_t a_hi_base = sb + SM_A_HI + a_off;
        const uint32_t a_lo_base = sb + SM_A_LO + a_off;
        const uint32_t b_hi_base = sb + SM_B_HI + b_off;
        const uint32_t b_lo_base = sb + SM_B_LO + b_off;
#pragma unroll
        for (int ks = 0; ks < 4; ks++) {
            uint32_t a[4][4], bh[2][4], bl[2][4];
            // pass 0: a_hi x b_hi
#pragma unroll
            for (int mb = 0; mb < 4; mb++)
                ldmx4(a[mb], a_hi_base + mb * (16 * T2_ROWBYTES) + ks * 32);
#pragma unroll
            for (int n2 = 0; n2 < 2; n2++)
                ldmx4(bh[n2], b_hi_base + n2 * (16 * T2_ROWBYTES) + ks * 32);
#pragma unroll
            for (int mb = 0; mb < 4; mb++)
#pragma unroll
                for (int nb = 0; nb < 4; nb++)
                    mma16816(acc[mb][nb], a[mb], bh[nb >> 1][(nb & 1) * 2],
                             bh[nb >> 1][(nb & 1) * 2 + 1]);
            // pass 1: a_hi x b_lo (reuse a)
#pragma unroll
            for (int n2 = 0; n2 < 2; n2++)
                ldmx4(bl[n2], b_lo_base + n2 * (16 * T2_ROWBYTES) + ks * 32);
#pragma unroll
            for (int mb = 0; mb < 4; mb++)
#pragma unroll
                for (int nb = 0; nb < 4; nb++)
                    mma16816(acc[mb][nb], a[mb], bl[nb >> 1][(nb & 1) * 2],
                             bl[nb >> 1][(nb & 1) * 2 + 1]);
            // pass 2: a_lo x b_hi (reuse bh, overwrite a)
#pragma unroll
            for (int mb = 0; mb < 4; mb++)
                ldmx4(a[mb], a_lo_base + mb * (16 * T2_ROWBYTES) + ks * 32);
#pragma unroll
            for (int mb = 0; mb < 4; mb++)
#pragma unroll
                for (int nb = 0; nb < 4; nb++)
                    mma16816(acc[mb][nb], a[mb], bh[nb >> 1][(nb & 1) * 2],
                             bh[nb >> 1][(nb & 1) * 2 + 1]);
        }
    }
    __syncthreads();   // smem max/min arrays initialized; tiles no longer read

    // ---- register-resident epilogue ----
    // C fragment layout: acc[mb][nb][q]: row = wm*64 + mb*16 + (lane>>2) + 8*(q>=2)
    //                                    col = wn*32 + nb*8 + 2*(lane&3) + (q&1)
    const float*    sqr  = (const float*)(smem + AUX_SQR);
    const float*    sqc  = (const float*)(smem + AUX_SQC);
    const int*      lr   = (const int*)(smem + AUX_LR);
    const int*      lc   = (const int*)(smem + AUX_LC);
    unsigned* sRowMax = (unsigned*)(smem + AUX_RMAX);
    unsigned* sRowMin = (unsigned*)(smem + AUX_RMIN);
    unsigned* sColMax = (unsigned*)(smem + AUX_CMAX);
    unsigned* sColMin = (unsigned*)(smem + AUX_CMIN);

    // column metadata (8 cols per thread; depends only on lane&3 and nb,q&1)
    float sqc_r[8]; int lc_r[8], gcol[8];
#pragma unroll
    for (int nb = 0; nb < 4; nb++)
#pragma unroll
        for (int q2 = 0; q2 < 2; q2++) {
            int j  = nb * 2 + q2;
            int cl = wn * 32 + nb * 8 + 2 * (lane & 3) + q2;
            sqc_r[j] = sqc[cl];
            lc_r[j]  = lc[cl];
            gcol[j]  = colBase + cl;
        }
    float cpm[8], cnm[8];
#pragma unroll
    for (int j = 0; j < 8; j++) { cpm[j] = 0.0f; cnm[j] = 1e30f; }

#pragma unroll
    for (int mb = 0; mb < 4; mb++) {
        const int row0 = wm * 64 + mb * 16 + (lane >> 2);
        const int row1 = row0 + 8;
        const float sq0 = sqr[row0], sq1 = sqr[row1];
        const int   l0  = lr[row0],  l1  = lr[row1];
        const int   gr0 = rowBase + row0, gr1 = rowBase + row1;
        float rp0 = 0.0f, rn0 = 1e30f, rp1 = 0.0f, rn1 = 1e30f;
#pragma unroll
        for (int nb = 0; nb < 4; nb++) {
#pragma unroll
            for (int q = 0; q < 4; q++) {
                const int   j   = nb * 2 + (q & 1);
                const bool  hi2 = (q >= 2);
                const float sqi = hi2 ? sq1 : sq0;
                const int   li  = hi2 ? l1 : l0;
                const int   gri = hi2 ? gr1 : gr0;
                float d2 = fmaxf(sqi + sqc_r[j] - 2.0f * acc[mb][nb][q], 0.0f);
                if (li == lc_r[j]) {
                    if (gri != gcol[j]) {
                        if (hi2) rp1 = fmaxf(rp1, d2); else rp0 = fmaxf(rp0, d2);
                        cpm[j] = fmaxf(cpm[j], d2);
                    }
                } else {
                    if (hi2) rn1 = fminf(rn1, d2); else rn0 = fminf(rn0, d2);
                    cnm[j] = fminf(cnm[j], d2);
                }
            }
        }
        // combine row results across the 4-lane quad (same rows, diff cols)
#pragma unroll
        for (int o = 1; o <= 2; o <<= 1) {
            rp0 = fmaxf(rp0, __shfl_xor_sync(0xffffffffu, rp0, o));
            rn0 = fminf(rn0, __shfl_xor_sync(0xffffffffu, rn0, o));
            rp1 = fmaxf(rp1, __shfl_xor_sync(0xffffffffu, rp1, o));
            rn1 = fminf(rn1, __shfl_xor_sync(0xffffffffu, rn1, o));
        }
        if ((lane & 3) == 0) {
            atomicMax(&sRowMax[row0], __float_as_uint(rp0));
            atomicMin(&sRowMin[row0], __float_as_uint(rn0));
            atomicMax(&sRowMax[row1], __float_as_uint(rp1));
            atomicMin(&sRowMin[row1], __float_as_uint(rn1));
        }
    }

    // combine col results across the 8 lanes sharing a col set (xor 4,8,16)
#pragma unroll
    for (int o = 4; o <= 16; o <<= 1)
#pragma unroll
        for (int j = 0; j < 8; j++) {
            cpm[j] = fmaxf(cpm[j], __shfl_xor_sync(0xffffffffu, cpm[j], o));
            cnm[j] = fminf(cnm[j], __shfl_xor_sync(0xffffffffu, cnm[j], o));
        }
    if (lane < 4) {
#pragma unroll
        for (int nb = 0; nb < 4; nb++)
#pragma unroll
            for (int q2 = 0; q2 < 2; q2++) {
                int j  = nb * 2 + q2;
                int cl = wn * 32 + nb * 8 + 2 * lane + q2;
                atomicMax(&sColMax[cl], __float_as_uint(cpm[j]));
                atomicMin(&sColMin[cl], __float_as_uint(cnm[j]));
            }
    }
    __syncthreads();

    // ---- push to global ----
    if (tid < 128) {
        atomicMax(&g_maxpos[rowBase + tid], sRowMax[tid]);
        atomicMin(&g_minneg[rowBase + tid], sRowMin[tid]);
    } else {
        int t = tid - 128;
        atomicMax(&g_maxpos[colBase + t], sColMax[t]);
        atomicMin(&g_minneg[colBase + t], sColMin[t]);
    }
}

// ---------------------------------------------------------------------------
// Kernel 3: per-row sqrt + hinge, mean over N.
// ---------------------------------------------------------------------------
__global__ void tl_final_kernel(const float* __restrict__ margin_ptr,
                                float* __restrict__ out) {
    const float m = *margin_ptr;
    float sum = 0.0f;
    for (int r = threadIdx.x; r < NN; r += 256) {
        float pos = sqrtf(__uint_as_float(g_maxpos[r]));
        float neg = sqrtf(__uint_as_float(g_minneg[r]));
        sum += fmaxf(pos - neg + m, 0.0f);
    }
    __shared__ float red[256];
    red[threadIdx.x] = sum;
    __syncthreads();
    for (int s = 128; s > 0; s >>= 1) {
        if (threadIdx.x < s) red[threadIdx.x] += red[threadIdx.x + s];
        __syncthreads();
    }
    if (threadIdx.x == 0) out[0] = red[0] / (float)NN;
}

// ---------------------------------------------------------------------------
extern "C" void kernel_launch(void* const* d_in, const int* in_sizes, int n_in,
                              void* d_out, int out_size) {
    const float* emb    = (const float*)d_in[0];
    const int*   labels = (const int*)d_in[1];
    const float* margin = (const float*)d_in[2];
    float*       out    = (float*)d_out;

    cudaFuncSetAttribute(tl_tile_mma, cudaFuncAttributeMaxDynamicSharedMemorySize,
                         SMEM_BYTES);

    tl_init_kernel<<<NN / 8, 256>>>(emb, labels);
    tl_tile_mma<<<NTRI, 256, SMEM_BYTES>>>();
    tl_final_kernel<<<1, 256>>>(margin, out);
}